// round 14
// baseline (speedup 1.0000x reference)
#include <cuda_runtime.h>

#define NN 32
#define DS 33                           // D stride (33 physical slots)
#define CC 1024
#define NT 1024
#define FULLM 0xffffffffu

// dynamic smem layout
#define OFF_ROWS 0                      // float [33][1024]  = 135168
#define OFF_D    135168                 // float [33][33]    = 4356 -> pad 4480
#define OFF_VAL  139648                 // u32   [2][32]     = 256
#define OFF_IDX  139904                 // u32   [2][32]     = 256
#define OFF_SQ   140160                 // float [33]        = 132 -> pad 160
#define OFF_L    140320                 // int   [2][32]     = 256
#define SMEM_TOTAL 140576

typedef unsigned long long u64;

__device__ __forceinline__ float warp_sum(float v) {
    #pragma unroll
    for (int o = 16; o; o >>= 1) v += __shfl_down_sync(FULLM, v, o);
    return v;
}

// three interleaved warp reductions (independent chains pipeline SHFL latency)
__device__ __forceinline__ void warp_sum3(float& a, float& b, float& c) {
    #pragma unroll
    for (int o = 16; o; o >>= 1) {
        a += __shfl_down_sync(FULLM, a, o);
        b += __shfl_down_sync(FULLM, b, o);
        c += __shfl_down_sync(FULLM, c, o);
    }
}

__global__ __launch_bounds__(NT, 1)
void merge_tree_kernel(const float* __restrict__ x,
                       const float* __restrict__ cw,
                       const float* __restrict__ cb,
                       float* __restrict__ out)
{
    extern __shared__ unsigned char sm_raw[];
    float*    rows = (float*)(sm_raw + OFF_ROWS);
    float*    D    = (float*)(sm_raw + OFF_D);        // [33][33], stride DS
    unsigned* vals = (unsigned*)(sm_raw + OFF_VAL);   // [2][32]
    unsigned* idxs = (unsigned*)(sm_raw + OFF_IDX);   // [2][32]
    float*    sq   = (float*)(sm_raw + OFF_SQ);       // [33]
    int*      Lb   = (int*)(sm_raw + OFF_L);          // [2][32]

    const int tid  = threadIdx.x;
    const int lane = tid & 31;
    const int warp = tid >> 5;
    const int b    = blockIdx.x;

    // ---- load batch rows (coalesced float4) ----
    {
        const float4* xb4 = (const float4*)(x + (size_t)b * (NN * CC));
        float4* r4 = (float4*)rows;
        #pragma unroll
        for (int i = tid; i < NN * CC / 4; i += NT) r4[i] = xb4[i];
    }
    const float w00 = cw[0], w01 = cw[1], w02 = cw[2];
    const float w10 = cw[3], w11 = cw[4], w12 = cw[5];
    const float bv  = cb[0];
    if (tid < NN) Lb[tid] = tid;                      // L buffer 0
    __syncthreads();

    // ---- cache own row in registers; norms (fp32, 4-chain) ----
    float4 rv[8];
    {
        const float4* r4w = (const float4*)(rows + warp * CC);
        #pragma unroll
        for (int k = 0; k < 8; k++) rv[k] = r4w[lane + 32 * k];
        float a0 = 0, a1 = 0, a2 = 0, a3 = 0;
        #pragma unroll
        for (int k = 0; k < 8; k++) {
            a0 = fmaf(rv[k].x, rv[k].x, a0);
            a1 = fmaf(rv[k].y, rv[k].y, a1);
            a2 = fmaf(rv[k].z, rv[k].z, a2);
            a3 = fmaf(rv[k].w, rv[k].w, a3);
        }
        float s = warp_sum((a0 + a1) + (a2 + a3));
        if (!lane) sq[warp] = s;
    }
    __syncthreads();

    // ---- initial gram, balanced rotation (each unordered pair once;
    //      FMA commutes so values match canonical order) ----
    {
        const float sqi = sq[warp];
        #pragma unroll 1
        for (int k = 1; k <= 16; k++) {
            if (k == 16 && warp >= 16) break;
            const int j = (warp + k) & 31;
            const float4* rj4 = (const float4*)(rows + j * CC);
            float a0 = 0, a1 = 0, a2 = 0, a3 = 0;
            #pragma unroll
            for (int q = 0; q < 8; q++) {
                float4 v = rj4[lane + 32 * q];
                a0 = fmaf(rv[q].x, v.x, a0);
                a1 = fmaf(rv[q].y, v.y, a1);
                a2 = fmaf(rv[q].z, v.z, a2);
                a3 = fmaf(rv[q].w, v.w, a3);
            }
            float dot = warp_sum((a0 + a1) + (a2 + a3));
            if (!lane) {
                float d2 = sqi + sq[j] - 2.0f * dot;
                float d  = sqrtf(fmaxf(d2, 0.f));
                D[warp * DS + j] = d;
                D[j * DS + warp] = d;
            }
        }
    }
    __syncthreads();

    // ---- pre-loop argmin partials into buffer 0 ----
    {
        unsigned kv = FULLM, ki = 0x3ffu;
        if (lane > warp) {
            kv = __float_as_uint(D[warp * DS + lane]);
            ki = (unsigned)((warp << 5) | lane);
        }
        unsigned wv = __reduce_min_sync(FULLM, kv);
        unsigned mm = __ballot_sync(FULLM, kv == wv);
        unsigned ci = ((mm >> lane) & 1) ? ki : FULLM;
        unsigned wi = __reduce_min_sync(FULLM, ci);
        if (!lane) { vals[warp] = wv; idxs[warp] = wi; }
    }
    __syncthreads();

    // ==== 31 merge steps, 2 barriers each (spare-slot, split P2) ====
    int n = NN;
    int par = 0;        // argmin partial parity
    int lpar = 0;       // L parity
    int spare = 32;     // always-free physical slot
    for (int step = 0; step < NN - 1; step++, n--) {
        unsigned* vcur = vals + par * 32;
        unsigned* icur = idxs + par * 32;
        par ^= 1;
        unsigned* vnxt = vals + par * 32;
        unsigned* inxt = idxs + par * 32;
        int* Lcur = Lb + lpar * 32;
        lpar ^= 1;
        int* Lnxt = Lb + lpar * 32;

        // ---------- P1 ----------
        // combine 32 partials -> global (value, lexicographic idx) min
        unsigned v  = vcur[lane];
        unsigned gm = __reduce_min_sync(FULLM, v);
        unsigned mk = __ballot_sync(FULLM, v == gm);
        unsigned cd = ((mk >> lane) & 1) ? icur[lane] : FULLM;
        unsigned gi = __reduce_min_sync(FULLM, cd);

        const int a   = (gi >> 5) & 31;
        const int bbj = gi & 31;
        const int ra  = Lcur[a];
        const int rb  = Lcur[bbj];
        const int dst = spare;                    // merged row -> spare slot
        // freed slot: normally L[a]; when a==1 the reference's sequential
        // perm-sets drop logical row 0 and KEEP row 1, so freed slot is L[0].
        spare = (a == 1) ? Lcur[0] : ra;

        // conv1d(2ch->1ch,k=3,SAME)+bias+relu, one elem/thread
        const float* Xa = rows + ra * CC;
        const float* Xb = rows + rb * CC;
        const int h = tid;
        float a1v = Xa[h], b1v = Xb[h];
        float a0v = (h > 0)      ? Xa[h - 1] : 0.f;
        float a2v = (h < CC - 1) ? Xa[h + 1] : 0.f;
        float b0v = (h > 0)      ? Xb[h - 1] : 0.f;
        float b2v = (h < CC - 1) ? Xb[h + 1] : 0.f;
        float m = fmaf(w00, a0v, fmaf(w01, a1v, fmaf(w02, a2v,
                  fmaf(w10, b0v, fmaf(w11, b1v, fmaf(w12, b2v, bv))))));
        m = fmaxf(m, 0.f);
        rows[dst * CC + h] = m;                   // no WAR: dst was spare

        if (tid < n - 1) {
            int nv;
            if (tid == 0) nv = dst;
            else {
                int pp  = tid + 1;
                int src = (pp == a) ? 0 : ((pp == bbj) ? 1 : pp);
                nv = Lcur[src];
            }
            Lnxt[tid] = nv;
        }
        __syncthreads();                          // bar 1: rows[dst], Lnxt visible

        // ---------- P2 (warps 0-15: dots, 2 survivors each;
        //             warps 16-31: scan, <=2 flat rows each) ----------
        const int cnt = n - 2;                    // next-config survivors 1..cnt
        if (cnt > 0) {
            // lane-resident survivor slot table, redistributed by shfl
            const int slv = (lane >= 1 && lane <= cnt) ? Lnxt[lane] : 0;
            u64 kk = 0xffffffffffffffffull;       // per-warp partial key

            if (warp >= 16) {
                // scan rows i = (warp-16)+1 and +16 (survivor-survivor pairs)
                #pragma unroll
                for (int r = 0; r < 2; r++) {
                    const int i = (warp - 16) + 1 + r * 16;
                    if (i <= cnt - 1) {
                        const int si = __shfl_sync(FULLM, slv, i);
                        unsigned kv = FULLM;
                        if (lane > i && lane <= cnt)
                            kv = __float_as_uint(D[si * DS + slv]);
                        unsigned wv = __reduce_min_sync(FULLM, kv);
                        unsigned mm = __ballot_sync(FULLM, kv == wv);
                        int jw = __ffs(mm) - 1;   // lowest lane = smallest j
                        u64 kc = ((u64)wv << 32) | (unsigned)((i << 5) | jw);
                        kk = min(kk, kc);
                    }
                }
            } else {
                const int j0 = 2 * warp;          // 0-based survivor index
                if (j0 < cnt) {
                    const int c1ok = (j0 + 1) < cnt;
                    const int s0 = __shfl_sync(FULLM, slv, 1 + j0);
                    const int s1 = __shfl_sync(FULLM, slv, c1ok ? (2 + j0) : (1 + j0));
                    const float4* rm  = (const float4*)(rows + dst * CC);
                    const float4* rs0 = (const float4*)(rows + s0 * CC);
                    const float4* rs1 = (const float4*)(rows + s1 * CC);
                    float A0=0,A1=0,A2=0,A3=0;    // dot(m, s0)
                    float B0=0,B1=0,B2=0,B3=0;    // dot(m, s1)
                    float M0=0,M1=0,M2=0,M3=0;    // |m|^2
                    #pragma unroll
                    for (int k = 0; k < 8; k++) {
                        float4 u  = rm [lane + 32 * k];
                        float4 v0 = rs0[lane + 32 * k];
                        float4 v1 = rs1[lane + 32 * k];
                        A0 = fmaf(u.x, v0.x, A0);
                        A1 = fmaf(u.y, v0.y, A1);
                        A2 = fmaf(u.z, v0.z, A2);
                        A3 = fmaf(u.w, v0.w, A3);
                        B0 = fmaf(u.x, v1.x, B0);
                        B1 = fmaf(u.y, v1.y, B1);
                        B2 = fmaf(u.z, v1.z, B2);
                        B3 = fmaf(u.w, v1.w, B3);
                        M0 = fmaf(u.x, u.x, M0);
                        M1 = fmaf(u.y, u.y, M1);
                        M2 = fmaf(u.z, u.z, M2);
                        M3 = fmaf(u.w, u.w, M3);
                    }
                    float d0  = (A0 + A1) + (A2 + A3);
                    float d1  = (B0 + B1) + (B2 + B3);
                    float msq = (M0 + M1) + (M2 + M3);
                    warp_sum3(d0, d1, msq);
                    if (!lane) {
                        float e0 = sqrtf(fmaxf(msq + sq[s0] - 2.0f * d0, 0.f));
                        D[dst * DS + s0] = e0;    // disjoint from scan reads
                        D[s0 * DS + dst] = e0;
                        kk = ((u64)__float_as_uint(e0) << 32)
                           | (unsigned)(1 + j0);  // pair (0, 1+j0)
                        if (c1ok) {
                            float e1 = sqrtf(fmaxf(msq + sq[s1] - 2.0f * d1, 0.f));
                            D[dst * DS + s1] = e1;
                            D[s1 * DS + dst] = e1;
                            u64 k1 = ((u64)__float_as_uint(e1) << 32)
                                   | (unsigned)(2 + j0);
                            kk = min(kk, k1);
                        }
                        if (warp == 0) sq[dst] = msq;  // persist merged norm
                    }
                }
            }

            if (!lane) {
                vnxt[warp] = (unsigned)(kk >> 32);
                inxt[warp] = (unsigned)(kk & 0x3ffu);
            }
        }
        __syncthreads();                          // bar 2
    }

    // final merged row lives at slot Lfinal[0]
    out[(size_t)b * CC + tid] = rows[(Lb + lpar * 32)[0] * CC + tid];
}

extern "C" void kernel_launch(void* const* d_in, const int* in_sizes, int n_in,
                              void* d_out, int out_size)
{
    const float* x  = (const float*)d_in[0];
    const float* cw = (const float*)d_in[1];
    const float* cb = (const float*)d_in[2];
    float* out = (float*)d_out;

    int B = in_sizes[0] / (NN * CC);

    cudaFuncSetAttribute(merge_tree_kernel,
                         cudaFuncAttributeMaxDynamicSharedMemorySize,
                         SMEM_TOTAL);
    merge_tree_kernel<<<B, NT, SMEM_TOTAL>>>(x, cw, cb, out);
}

// round 15
// speedup vs baseline: 1.2685x; 1.2685x over previous
#include <cuda_runtime.h>

#define NN 32
#define DS 33                           // D stride (33 physical slots)
#define CC 1024
#define NT 512
#define FULLM 0xffffffffu

// dynamic smem layout
#define OFF_ROWS 0                      // float [33][1024]  = 135168
#define OFF_D    135168                 // float [33][33]    = 4356 -> pad 4480
#define OFF_VAL  139648                 // u32   [2][32]     = 256
#define OFF_IDX  139904                 // u32   [2][32]     = 256
#define OFF_SQ   140160                 // float [33]        = 132 -> pad 160
#define OFF_L    140320                 // int   [2][32]     = 256
#define SMEM_TOTAL 140576

typedef unsigned long long u64;

__device__ __forceinline__ float warp_sum(float v) {
    #pragma unroll
    for (int o = 16; o; o >>= 1) v += __shfl_down_sync(FULLM, v, o);
    return v;
}

__device__ __forceinline__ void warp_sum3(float& a, float& b, float& c) {
    #pragma unroll
    for (int o = 16; o; o >>= 1) {
        a += __shfl_down_sync(FULLM, a, o);
        b += __shfl_down_sync(FULLM, b, o);
        c += __shfl_down_sync(FULLM, c, o);
    }
}

__device__ __forceinline__ void warp_sum4(float& a, float& b, float& c, float& d) {
    #pragma unroll
    for (int o = 16; o; o >>= 1) {
        a += __shfl_down_sync(FULLM, a, o);
        b += __shfl_down_sync(FULLM, b, o);
        c += __shfl_down_sync(FULLM, c, o);
        d += __shfl_down_sync(FULLM, d, o);
    }
}

__global__ __launch_bounds__(NT, 1)
void merge_tree_kernel(const float* __restrict__ x,
                       const float* __restrict__ cw,
                       const float* __restrict__ cb,
                       float* __restrict__ out)
{
    extern __shared__ unsigned char sm_raw[];
    float*    rows = (float*)(sm_raw + OFF_ROWS);
    float*    D    = (float*)(sm_raw + OFF_D);        // [33][33], stride DS
    unsigned* vals = (unsigned*)(sm_raw + OFF_VAL);   // [2][32] (16 used)
    unsigned* idxs = (unsigned*)(sm_raw + OFF_IDX);
    float*    sq   = (float*)(sm_raw + OFF_SQ);       // [33]
    int*      Lb   = (int*)(sm_raw + OFF_L);          // [2][32]

    const int tid  = threadIdx.x;
    const int lane = tid & 31;
    const int warp = tid >> 5;                        // 0..15
    const int b    = blockIdx.x;

    // ---- load batch rows (coalesced float4, 16 iters) ----
    {
        const float4* xb4 = (const float4*)(x + (size_t)b * (NN * CC));
        float4* r4 = (float4*)rows;
        #pragma unroll
        for (int i = tid; i < NN * CC / 4; i += NT) r4[i] = xb4[i];
    }
    const float w00 = cw[0], w01 = cw[1], w02 = cw[2];
    const float w10 = cw[3], w11 = cw[4], w12 = cw[5];
    const float bv  = cb[0];
    if (tid < NN) Lb[tid] = tid;                      // L buffer 0
    __syncthreads();

    // ---- cache TWO rows per warp (2I, 2I+1); norms + diag dot ----
    float4 c0[8], c1[8];
    float diagdot;                                    // valid on lane 0
    {
        const float4* r0 = (const float4*)(rows + (2 * warp) * CC);
        const float4* r1 = (const float4*)(rows + (2 * warp + 1) * CC);
        #pragma unroll
        for (int k = 0; k < 8; k++) { c0[k] = r0[lane + 32 * k]; c1[k] = r1[lane + 32 * k]; }

        float n0a=0,n0b=0,n0c=0,n0d=0;
        float n1a=0,n1b=0,n1c=0,n1d=0;
        float dda=0,ddb=0,ddc=0,ddd=0;
        #pragma unroll
        for (int k = 0; k < 8; k++) {
            n0a = fmaf(c0[k].x, c0[k].x, n0a);
            n0b = fmaf(c0[k].y, c0[k].y, n0b);
            n0c = fmaf(c0[k].z, c0[k].z, n0c);
            n0d = fmaf(c0[k].w, c0[k].w, n0d);
            n1a = fmaf(c1[k].x, c1[k].x, n1a);
            n1b = fmaf(c1[k].y, c1[k].y, n1b);
            n1c = fmaf(c1[k].z, c1[k].z, n1c);
            n1d = fmaf(c1[k].w, c1[k].w, n1d);
            dda = fmaf(c0[k].x, c1[k].x, dda);
            ddb = fmaf(c0[k].y, c1[k].y, ddb);
            ddc = fmaf(c0[k].z, c1[k].z, ddc);
            ddd = fmaf(c0[k].w, c1[k].w, ddd);
        }
        float s0 = (n0a + n0b) + (n0c + n0d);
        float s1 = (n1a + n1b) + (n1c + n1d);
        float sd = (dda + ddb) + (ddc + ddd);
        warp_sum3(s0, s1, sd);
        if (!lane) { sq[2 * warp] = s0; sq[2 * warp + 1] = s1; }
        diagdot = sd;
    }
    __syncthreads();                                  // sq[] visible

    // diag pair distance (2I, 2I+1)
    if (!lane) {
        int i = 2 * warp, j = 2 * warp + 1;
        float d2v = sq[i] + sq[j] - 2.0f * diagdot;
        float d = sqrtf(fmaxf(d2v, 0.f));
        D[i * DS + j] = d;
        D[j * DS + i] = d;
    }

    // ---- gram off-diag: supertile rotation, 2x2 tiles ----
    // warp I handles supertile pair (I, (I+k)&15), k=1..7 (all), k=8 (I<8).
    {
        #pragma unroll 1
        for (int k = 1; k <= 8; k++) {
            if (k == 8 && warp >= 8) break;
            const int J = (warp + k) & 15;
            const float4* v0p = (const float4*)(rows + (2 * J) * CC);
            const float4* v1p = (const float4*)(rows + (2 * J + 1) * CC);
            float p00a=0,p00b=0,p00c=0,p00d=0;
            float p01a=0,p01b=0,p01c=0,p01d=0;
            float p10a=0,p10b=0,p10c=0,p10d=0;
            float p11a=0,p11b=0,p11c=0,p11d=0;
            #pragma unroll
            for (int q = 0; q < 8; q++) {
                float4 v0 = v0p[lane + 32 * q];
                float4 v1 = v1p[lane + 32 * q];
                p00a = fmaf(c0[q].x, v0.x, p00a);
                p00b = fmaf(c0[q].y, v0.y, p00b);
                p00c = fmaf(c0[q].z, v0.z, p00c);
                p00d = fmaf(c0[q].w, v0.w, p00d);
                p01a = fmaf(c0[q].x, v1.x, p01a);
                p01b = fmaf(c0[q].y, v1.y, p01b);
                p01c = fmaf(c0[q].z, v1.z, p01c);
                p01d = fmaf(c0[q].w, v1.w, p01d);
                p10a = fmaf(c1[q].x, v0.x, p10a);
                p10b = fmaf(c1[q].y, v0.y, p10b);
                p10c = fmaf(c1[q].z, v0.z, p10c);
                p10d = fmaf(c1[q].w, v0.w, p10d);
                p11a = fmaf(c1[q].x, v1.x, p11a);
                p11b = fmaf(c1[q].y, v1.y, p11b);
                p11c = fmaf(c1[q].z, v1.z, p11c);
                p11d = fmaf(c1[q].w, v1.w, p11d);
            }
            float s00 = (p00a + p00b) + (p00c + p00d);
            float s01 = (p01a + p01b) + (p01c + p01d);
            float s10 = (p10a + p10b) + (p10c + p10d);
            float s11 = (p11a + p11b) + (p11c + p11d);
            warp_sum4(s00, s01, s10, s11);
            if (!lane) {
                int i0 = 2 * warp, i1 = 2 * warp + 1, j0 = 2 * J, j1 = 2 * J + 1;
                float e00 = sqrtf(fmaxf(sq[i0] + sq[j0] - 2.0f * s00, 0.f));
                float e01 = sqrtf(fmaxf(sq[i0] + sq[j1] - 2.0f * s01, 0.f));
                float e10 = sqrtf(fmaxf(sq[i1] + sq[j0] - 2.0f * s10, 0.f));
                float e11 = sqrtf(fmaxf(sq[i1] + sq[j1] - 2.0f * s11, 0.f));
                D[i0 * DS + j0] = e00; D[j0 * DS + i0] = e00;
                D[i0 * DS + j1] = e01; D[j1 * DS + i0] = e01;
                D[i1 * DS + j0] = e10; D[j0 * DS + i1] = e10;
                D[i1 * DS + j1] = e11; D[j1 * DS + i1] = e11;
            }
        }
    }
    __syncthreads();                                  // D complete

    // ---- pre-loop argmin partials: warp w scans rows w and w+16 ----
    {
        u64 kk = 0xffffffffffffffffull;
        {
            unsigned kv = (lane > warp) ? __float_as_uint(D[warp * DS + lane]) : FULLM;
            unsigned wv = __reduce_min_sync(FULLM, kv);
            unsigned mm = __ballot_sync(FULLM, kv == wv);
            if (wv != FULLM) {
                int jw = __ffs(mm) - 1;
                kk = ((u64)wv << 32) | (unsigned)((warp << 5) | jw);
            }
        }
        {
            const int i = warp + 16;
            if (i <= NN - 2) {
                unsigned kv = (lane > i) ? __float_as_uint(D[i * DS + lane]) : FULLM;
                unsigned wv = __reduce_min_sync(FULLM, kv);
                unsigned mm = __ballot_sync(FULLM, kv == wv);
                if (wv != FULLM) {
                    int jw = __ffs(mm) - 1;
                    u64 kc = ((u64)wv << 32) | (unsigned)((i << 5) | jw);
                    kk = min(kk, kc);
                }
            }
        }
        if (!lane) { vals[warp] = (unsigned)(kk >> 32); idxs[warp] = (unsigned)(kk & 0x3ffu); }
    }
    __syncthreads();

    // ==== 31 merge steps, 2 barriers each ====
    int n = NN;
    int par = 0;
    int lpar = 0;
    int spare = 32;
    const int h0 = tid, h1 = tid + NT;
    for (int step = 0; step < NN - 1; step++, n--) {
        unsigned* vcur = vals + par * 32;
        unsigned* icur = idxs + par * 32;
        par ^= 1;
        unsigned* vnxt = vals + par * 32;
        unsigned* inxt = idxs + par * 32;
        int* Lcur = Lb + lpar * 32;
        lpar ^= 1;
        int* Lnxt = Lb + lpar * 32;

        // ---------- P1 ----------
        unsigned v  = (lane < 16) ? vcur[lane] : FULLM;
        unsigned gm = __reduce_min_sync(FULLM, v);
        unsigned mk = __ballot_sync(FULLM, v == gm);
        unsigned cd = ((mk >> lane) & 1) ? icur[lane] : FULLM;
        unsigned gi = __reduce_min_sync(FULLM, cd);

        const int a   = (gi >> 5) & 31;
        const int bbj = gi & 31;
        const int ra  = Lcur[a];
        const int rb  = Lcur[bbj];
        const int dst = spare;
        // freed slot: normally L[a]; when a==1 the reference's sequential
        // perm-sets drop logical row 0 and KEEP row 1, so freed slot is L[0].
        spare = (a == 1) ? Lcur[0] : ra;

        // conv1d(2ch->1ch,k=3,SAME)+bias+relu, TWO elems/thread
        const float* Xa = rows + ra * CC;
        const float* Xb = rows + rb * CC;
        float m0, m1;
        {
            float a1v = Xa[h0], b1v = Xb[h0];
            float a0v = (h0 > 0) ? Xa[h0 - 1] : 0.f;
            float a2v = Xa[h0 + 1];                   // h0 <= 511 < 1023
            float b0v = (h0 > 0) ? Xb[h0 - 1] : 0.f;
            float b2v = Xb[h0 + 1];
            m0 = fmaf(w00, a0v, fmaf(w01, a1v, fmaf(w02, a2v,
                 fmaf(w10, b0v, fmaf(w11, b1v, fmaf(w12, b2v, bv))))));
            m0 = fmaxf(m0, 0.f);
        }
        {
            float a1v = Xa[h1], b1v = Xb[h1];
            float a0v = Xa[h1 - 1];                   // h1 >= 512 > 0
            float a2v = (h1 < CC - 1) ? Xa[h1 + 1] : 0.f;
            float b0v = Xb[h1 - 1];
            float b2v = (h1 < CC - 1) ? Xb[h1 + 1] : 0.f;
            m1 = fmaf(w00, a0v, fmaf(w01, a1v, fmaf(w02, a2v,
                 fmaf(w10, b0v, fmaf(w11, b1v, fmaf(w12, b2v, bv))))));
            m1 = fmaxf(m1, 0.f);
        }
        rows[dst * CC + h0] = m0;                     // no WAR: dst was spare
        rows[dst * CC + h1] = m1;

        if (tid < n - 1) {
            int nv;
            if (tid == 0) nv = dst;
            else {
                int pp  = tid + 1;
                int src = (pp == a) ? 0 : ((pp == bbj) ? 1 : pp);
                nv = Lcur[src];
            }
            Lnxt[tid] = nv;
        }
        __syncthreads();                              // bar 1

        // ---------- P2: warps 0-9 dots (3 surv, m cached); 10-15 scan ----------
        const int cnt = n - 2;                        // survivors 1..cnt
        if (cnt > 0) {
            const int slv = (lane >= 1 && lane <= cnt) ? Lnxt[lane] : 0;
            u64 kk = 0xffffffffffffffffull;

            if (warp < 10) {
                const int j0 = 3 * warp;              // 0-based survivor idx
                if (j0 < cnt) {
                    const int c1ok = (j0 + 1) < cnt;
                    const int c2ok = (j0 + 2) < cnt;
                    const int s0 = __shfl_sync(FULLM, slv, 1 + j0);
                    const int s1 = __shfl_sync(FULLM, slv, c1ok ? (2 + j0) : (1 + j0));
                    const int s2 = __shfl_sync(FULLM, slv, c2ok ? (3 + j0) : (1 + j0));
                    // cache m row in registers
                    float4 mv[8];
                    const float4* rm = (const float4*)(rows + dst * CC);
                    #pragma unroll
                    for (int k = 0; k < 8; k++) mv[k] = rm[lane + 32 * k];

                    const float4* rs0 = (const float4*)(rows + s0 * CC);
                    const float4* rs1 = (const float4*)(rows + s1 * CC);
                    const float4* rs2 = (const float4*)(rows + s2 * CC);
                    float A0=0,A1=0,A2=0,A3=0;
                    float B0=0,B1=0,B2=0,B3=0;
                    float C0=0,C1=0,C2=0,C3=0;
                    float M0=0,M1=0,M2=0,M3=0;
                    #pragma unroll
                    for (int k = 0; k < 8; k++) {
                        float4 u  = mv[k];
                        float4 v0 = rs0[lane + 32 * k];
                        float4 v1 = rs1[lane + 32 * k];
                        float4 v2 = rs2[lane + 32 * k];
                        A0 = fmaf(u.x, v0.x, A0);
                        A1 = fmaf(u.y, v0.y, A1);
                        A2 = fmaf(u.z, v0.z, A2);
                        A3 = fmaf(u.w, v0.w, A3);
                        B0 = fmaf(u.x, v1.x, B0);
                        B1 = fmaf(u.y, v1.y, B1);
                        B2 = fmaf(u.z, v1.z, B2);
                        B3 = fmaf(u.w, v1.w, B3);
                        C0 = fmaf(u.x, v2.x, C0);
                        C1 = fmaf(u.y, v2.y, C1);
                        C2 = fmaf(u.z, v2.z, C2);
                        C3 = fmaf(u.w, v2.w, C3);
                        M0 = fmaf(u.x, u.x, M0);
                        M1 = fmaf(u.y, u.y, M1);
                        M2 = fmaf(u.z, u.z, M2);
                        M3 = fmaf(u.w, u.w, M3);
                    }
                    float d0  = (A0 + A1) + (A2 + A3);
                    float d1  = (B0 + B1) + (B2 + B3);
                    float d2s = (C0 + C1) + (C2 + C3);
                    float msq = (M0 + M1) + (M2 + M3);
                    warp_sum4(d0, d1, d2s, msq);
                    if (!lane) {
                        float e0 = sqrtf(fmaxf(msq + sq[s0] - 2.0f * d0, 0.f));
                        D[dst * DS + s0] = e0;
                        D[s0 * DS + dst] = e0;
                        kk = ((u64)__float_as_uint(e0) << 32) | (unsigned)(1 + j0);
                        if (c1ok) {
                            float e1 = sqrtf(fmaxf(msq + sq[s1] - 2.0f * d1, 0.f));
                            D[dst * DS + s1] = e1;
                            D[s1 * DS + dst] = e1;
                            u64 k1 = ((u64)__float_as_uint(e1) << 32) | (unsigned)(2 + j0);
                            kk = min(kk, k1);
                        }
                        if (c2ok) {
                            float e2 = sqrtf(fmaxf(msq + sq[s2] - 2.0f * d2s, 0.f));
                            D[dst * DS + s2] = e2;
                            D[s2 * DS + dst] = e2;
                            u64 k2 = ((u64)__float_as_uint(e2) << 32) | (unsigned)(3 + j0);
                            kk = min(kk, k2);
                        }
                        if (warp == 0) sq[dst] = msq; // persist merged norm
                    }
                }
            } else {
                // scan warps: rows i = (warp-10)+1 + 6r, r=0..4 (flat, independent)
                #pragma unroll
                for (int r = 0; r < 5; r++) {
                    const int i = (warp - 10) + 1 + 6 * r;
                    if (i <= cnt - 1) {
                        const int si = __shfl_sync(FULLM, slv, i);
                        unsigned kv = FULLM;
                        if (lane > i && lane <= cnt)
                            kv = __float_as_uint(D[si * DS + slv]);
                        unsigned wv = __reduce_min_sync(FULLM, kv);
                        unsigned mm = __ballot_sync(FULLM, kv == wv);
                        if (wv != FULLM) {
                            int jw = __ffs(mm) - 1;
                            u64 kc = ((u64)wv << 32) | (unsigned)((i << 5) | jw);
                            kk = min(kk, kc);
                        }
                    }
                }
            }

            if (!lane) {
                vnxt[warp] = (unsigned)(kk >> 32);
                inxt[warp] = (unsigned)(kk & 0x3ffu);
            }
        }
        __syncthreads();                              // bar 2
    }

    // final merged row lives at slot Lfinal[0]
    {
        const int fs = (Lb + lpar * 32)[0];
        out[(size_t)b * CC + h0] = rows[fs * CC + h0];
        out[(size_t)b * CC + h1] = rows[fs * CC + h1];
    }
}

extern "C" void kernel_launch(void* const* d_in, const int* in_sizes, int n_in,
                              void* d_out, int out_size)
{
    const float* x  = (const float*)d_in[0];
    const float* cw = (const float*)d_in[1];
    const float* cb = (const float*)d_in[2];
    float* out = (float*)d_out;

    int B = in_sizes[0] / (NN * CC);

    cudaFuncSetAttribute(merge_tree_kernel,
                         cudaFuncAttributeMaxDynamicSharedMemorySize,
                         SMEM_TOTAL);
    merge_tree_kernel<<<B, NT, SMEM_TOTAL>>>(x, cw, cb, out);
}